// round 4
// baseline (speedup 1.0000x reference)
#include <cuda_runtime.h>

// Batched Thomas tridiagonal solve, B=2048, N=8192.
//   a_i = alpha[i-1]^2, b_i = 1 + alpha[i]^3, c_i = alpha[i+1]^2 + 2 alpha[i+1]
// Diagonal dominance => chunked solve with HF=16 forward / HB=32 backward halos.
//
// Continuant (D/S) formulation removes rcp from the recurrence chain:
//   D_i = b_i D_{i-1} - (a_i c_{i-1}) D_{i-2}      (cp_i = c_i D_{i-1} / D_i)
//   S_i = f_i D_{i-1} - a_i S_{i-1}                (dp_i = S_i / D_i)
// Chain = 1 FMA / step. rcp only at checkpoints / phase-2 normalization.

#define N_COLSK 8192
#define L_OWN   128
#define HF      16
#define SPAN_C  177                 // HF + 128 + 32 + 1, odd pitch -> conflict-free
#define TPB     128
#define NTILES  10

#define SM_F    (TPB * SPAN_C)                  // f slice after alpha tile
#define SM_CK   (TPB * SPAN_C + SPAN_C + 3)     // checkpoint arrays
#define CKOFF   (NTILES * TPB)                  // dp checkpoints after cp checkpoints
#define SMEM_FLOATS (SM_CK + 2 * NTILES * TPB)
#define SMEM_BYTES  (SMEM_FLOATS * 4)

__device__ __forceinline__ float frcp(float x) {
    float r; asm("rcp.approx.f32 %0, %1;" : "=f"(r) : "f"(x)); return r;
}

__global__ __launch_bounds__(TPB)
void thomas_chunk_kernel(const float* __restrict__ alpha,
                         const float* __restrict__ f,
                         float* __restrict__ out)
{
    extern __shared__ float smem[];
    float* fS  = smem + SM_F;
    float* ckS = smem + SM_CK;

    const int tid  = threadIdx.x;
    const int cc   = blockIdx.x;                 // chunk column (0..63)
    const int row0 = blockIdx.y * TPB;
    const int s    = cc * L_OWN;
    const int col0 = s - HF;                     // first staged col (>= -16)

    // ---- stage alpha tile: per-iteration, lanes read consecutive cols of one
    //      row (coalesced LDG) and write consecutive smem banks (no conflict).
    //      Out-of-range cols staged as 0 -> boundary conditions fall out free.
    {
        const int c1 = col0 + tid;
        const int c2 = col0 + TPB + tid;
        const bool p1 = (c1 >= 0) & (c1 < N_COLSK);
        const bool p2 = (tid < SPAN_C - TPB) & (c2 < N_COLSK);
        const float* ap = alpha + (size_t)row0 * N_COLSK;
        float* sp = smem;
        for (int r = 0; r < TPB; ++r) {
            sp[tid] = p1 ? ap[c1] : 0.0f;
            if (tid < SPAN_C - TPB) sp[TPB + tid] = p2 ? ap[c2] : 0.0f;
            ap += N_COLSK; sp += SPAN_C;
        }
        fS[tid] = p1 ? f[c1] : 0.0f;
        if (tid < SPAN_C - TPB) fS[TPB + tid] = p2 ? f[c2] : 0.0f;
    }
    __syncthreads();

    const float* sA = smem + tid * SPAN_C;

    // ================= phase 1: forward continuant sweep =================
    float Dmm = 0.0f, Dm = 1.0f, S = 0.0f;       // D_{-2}, D_{-1}, S_{-1}
    float sqim1 = 0.0f;                          // alpha[i-1]^2 (halo cut)
    float al  = sA[0];
    float sqi = al * al;

#define FSTEP(RC) do {                                   \
        float alp1 = sA[(RC) + 1];                       \
        float fv   = fS[(RC)];                           \
        float sq1  = alp1 * alp1;                        \
        float bi   = fmaf(al, sqi, 1.0f);                \
        float cim1 = fmaf(2.0f, al, sqi);                \
        float t    = (sqim1 * cim1) * Dmm;               \
        float Dn   = fmaf(bi, Dm, -t);                   \
        float Sn   = fmaf(-sqim1, S, fv * Dm);           \
        Dmm = Dm; Dm = Dn; S = Sn;                       \
        sqim1 = sqi; sqi = sq1; al = alp1;               \
    } while (0)

    #pragma unroll
    for (int rc = 0; rc < HF; ++rc) FSTEP(rc);           // left halo warmup

    for (int k = 0; k < NTILES; ++k) {
        // checkpoint (cp, dp) entering this tile; rcp off the recurrence chain
        float r    = frcp(Dm);
        float cim1 = fmaf(2.0f, al, sqi);                // c_{base-1}
        ckS[k * TPB + tid]         = (cim1 * Dmm) * r;   // cp_in
        ckS[CKOFF + k * TPB + tid] = S * r;              // dp_in
        const int base = HF + (k << 4);
        #pragma unroll
        for (int j = 0; j < 16; ++j) FSTEP(base + j);
    }
#undef FSTEP

    // ======= phase 2: per tile (desc): recompute cp/dp, back-substitute ======
    float u = 0.0f;                                      // halo cut at top
    for (int k = NTILES - 1; k >= 0; --k) {
        const int base = HF + (k << 4);
        const float cp_in = ckS[k * TPB + tid];
        const float dp_in = ckS[CKOFF + k * TPB + tid];

        float al2   = sA[base];
        float sq2   = al2 * al2;
        float alm   = sA[base - 1];
        float sm1   = alm * alm;                         // a_base = alpha[base-1]^2
        float cpl[16], dpl[16];
        float dmm, dm, sl, qim1, qi, a2;
        {   // j = 0: fold incoming (cp_in, dp_in);  D~_{-1} = 1
            float alp1 = sA[base + 1];
            float fv   = fS[base];
            float sq1  = alp1 * alp1;
            float bi   = fmaf(al2, sq2, 1.0f);
            float D0   = fmaf(-sm1, cp_in, bi);          // den_0
            float S0   = fmaf(-sm1, dp_in, fv);
            float r    = frcp(D0);
            float cj   = fmaf(2.0f, alp1, sq1);          // c_0 (uses alpha[base+1])
            cpl[0] = cj * r;                             // c_0 * D~_{-1} / D~_0
            dpl[0] = S0 * r;
            dmm = 1.0f; dm = D0; sl = S0;
            qim1 = sq2; qi = sq1; a2 = alp1;
        }
        #pragma unroll
        for (int j = 1; j < 16; ++j) {
            float alp1 = sA[base + j + 1];
            float fv   = fS[base + j];
            float sq1  = alp1 * alp1;
            float bi   = fmaf(a2, qi, 1.0f);
            float cim1 = fmaf(2.0f, a2, qi);
            float t    = (qim1 * cim1) * dmm;
            float dn   = fmaf(bi, dm, -t);
            float sn   = fmaf(-qim1, sl, fv * dm);
            float r    = frcp(dn);
            float cj   = fmaf(2.0f, alp1, sq1);
            cpl[j] = (cj * dm) * r;
            dpl[j] = sn * r;
            dmm = dm; dm = dn; sl = sn;
            qim1 = qi; qi = sq1; a2 = alp1;
        }
        #pragma unroll
        for (int j = 15; j >= 0; --j) {
            u = fmaf(-cpl[j], u, dpl[j]);
            dpl[j] = u;
        }
        if (k < 8) {                                     // owned tiles only
            float4* o4 = reinterpret_cast<float4*>(
                out + (size_t)(row0 + tid) * N_COLSK + s + (k << 4));
            o4[0] = make_float4(dpl[0],  dpl[1],  dpl[2],  dpl[3]);
            o4[1] = make_float4(dpl[4],  dpl[5],  dpl[6],  dpl[7]);
            o4[2] = make_float4(dpl[8],  dpl[9],  dpl[10], dpl[11]);
            o4[3] = make_float4(dpl[12], dpl[13], dpl[14], dpl[15]);
        }
    }
}

extern "C" void kernel_launch(void* const* d_in, const int* in_sizes, int n_in,
                              void* d_out, int out_size)
{
    const float* alpha = (const float*)d_in[0];
    const float* f     = (const float*)d_in[1];
    float* out         = (float*)d_out;

    static int smem_set = 0;
    if (!smem_set) {
        cudaFuncSetAttribute(thomas_chunk_kernel,
                             cudaFuncAttributeMaxDynamicSharedMemorySize,
                             SMEM_BYTES);
        smem_set = 1;
    }

    dim3 grid(N_COLSK / L_OWN, 2048 / TPB);              // (64, 16)
    thomas_chunk_kernel<<<grid, TPB, SMEM_BYTES>>>(alpha, f, out);
}

// round 6
// speedup vs baseline: 5.7684x; 5.7684x over previous
#include <cuda_runtime.h>
#include <cstdint>

// Batched Thomas tridiagonal solve, B=2048, N=8192.
//   a_i = alpha[i-1]^2, b_i = 1 + alpha[i]^3, c_i = alpha[i+1]^2 + 2 alpha[i+1]
// Diagonal dominance (alpha in [0,0.3)) => chunked solve, HF=16 forward halo,
// HB=32 backward halo, fully parallel over (row, chunk).
//
// Continuant (D/S) formulation keeps the recurrence chain at 1 FMA/step:
//   D_i = b_i D_{i-1} - (a_i c_{i-1}) D_{i-2},  S_i = f_i D_{i-1} - a_i S_{i-1}
//   cp_i = c_i D_{i-1}/D_i,  dp_i = S_i/D_i   (rcp off the critical chain)
//
// cp.async tile staging (no serial LDG->STS chain, no integer div), and
// __launch_bounds__(TPB, 2) so phase-2 tile arrays stay in registers.

#define N_COLSK 8192
#define L_OWN   128
#define HF      16
#define SPAN_C  177                 // HF + 128 + 32 + 1; odd pitch -> conflict-free LDS
#define TPB     128
#define NTILES  10
#define TAIL_C  (SPAN_C - TPB)      // 49

#define SM_F    (TPB * SPAN_C)                      // f slice
#define SM_CK   (SM_F + SPAN_C + 3)                 // checkpoints (cp then dp)
#define CKOFF   (NTILES * TPB)
#define SM_DUMP (SM_CK + 2 * NTILES * TPB)          // dump slots for masked lanes
#define SMEM_FLOATS (SM_DUMP + TPB)
#define SMEM_BYTES  (SMEM_FLOATS * 4)

__device__ __forceinline__ float frcp(float x) {
    float r; asm("rcp.approx.f32 %0, %1;" : "=f"(r) : "f"(x)); return r;
}

// cp.async 4 bytes; src_sz = 0 zero-fills the destination (OOB handling).
__device__ __forceinline__ void cpa4(unsigned int saddr, const float* g, int src_sz) {
    asm volatile("cp.async.ca.shared.global [%0], [%1], 4, %2;"
                 :: "r"(saddr), "l"(g), "r"(src_sz));
}

__global__ __launch_bounds__(TPB, 2)
void thomas_chunk_kernel(const float* __restrict__ alpha,
                         const float* __restrict__ f,
                         float* __restrict__ out)
{
    extern __shared__ float smem[];
    float* fS  = smem + SM_F;
    float* ckS = smem + SM_CK;

    const int tid  = threadIdx.x;
    const int cc   = blockIdx.x;                 // chunk column (0..63)
    const int row0 = blockIdx.y * TPB;
    const int s    = cc * L_OWN;
    const int col0 = s - HF;                     // first staged col (>= -16)

    // ================= cp.async staging =================
    {
        const unsigned int smb  = (unsigned int)__cvta_generic_to_shared(smem);
        const unsigned int dump = smb + (unsigned int)(SM_DUMP + tid) * 4u;

        const int c1 = col0 + tid;                       // lane's first column
        const int c2 = col0 + TPB + tid;                 // lane's second column
        const int sz1 = (c1 >= 0 && c1 < N_COLSK) ? 4 : 0;
        const bool l2 = (tid < TAIL_C);
        const int sz2 = (l2 && c2 < N_COLSK) ? 4 : 0;
        const int c1c = max(0, min(c1, N_COLSK - 1));    // clamped (safe addr)
        const int c2c = max(0, min(c2, N_COLSK - 1));

        const float* g1 = alpha + (size_t)row0 * N_COLSK + c1c;
        const float* g2 = alpha + (size_t)row0 * N_COLSK + c2c;
        unsigned int s1 = smb + (unsigned int)tid * 4u;
        unsigned int s2 = l2 ? (smb + (unsigned int)(TPB + tid) * 4u) : dump;
        const unsigned int step2 = l2 ? (SPAN_C * 4u) : 0u;

        #pragma unroll 4
        for (int r = 0; r < TPB; ++r) {
            cpa4(s1, g1, sz1);
            cpa4(s2, g2, sz2);
            s1 += SPAN_C * 4u;
            s2 += step2;
            g1 += N_COLSK; g2 += N_COLSK;
        }
        // f slice (broadcast rhs)
        const unsigned int fsb = smb + SM_F * 4u;
        cpa4(fsb + (unsigned int)tid * 4u, f + c1c, sz1);
        cpa4(l2 ? (fsb + (unsigned int)(TPB + tid) * 4u) : dump, f + c2c, sz2);

        asm volatile("cp.async.commit_group;");
        asm volatile("cp.async.wait_group 0;");
    }
    __syncthreads();

    const float* sA = smem + tid * SPAN_C;

    // ================= phase 1: forward continuant sweep =================
    float Dmm = 0.0f, Dm = 1.0f, S = 0.0f;       // D_{-2}, D_{-1}, S_{-1}
    float sqim1 = 0.0f;                          // alpha[i-1]^2 (halo cut)
    float al  = sA[0];
    float sqi = al * al;

#define FSTEP(RC) do {                                   \
        float alp1 = sA[(RC) + 1];                       \
        float fv   = fS[(RC)];                           \
        float sq1  = alp1 * alp1;                        \
        float bi   = fmaf(al, sqi, 1.0f);                \
        float cim1 = fmaf(2.0f, al, sqi);                \
        float t    = (sqim1 * cim1) * Dmm;               \
        float Dn   = fmaf(bi, Dm, -t);                   \
        float Sn   = fmaf(-sqim1, S, fv * Dm);           \
        Dmm = Dm; Dm = Dn; S = Sn;                       \
        sqim1 = sqi; sqi = sq1; al = alp1;               \
    } while (0)

    #pragma unroll
    for (int rc = 0; rc < HF; ++rc) FSTEP(rc);           // left halo warmup

    for (int k = 0; k < NTILES; ++k) {
        // checkpoint (cp, dp) entering this tile (rcp off the chain)
        float r    = frcp(Dm);
        float cim1 = fmaf(2.0f, al, sqi);                // c_{base-1}
        ckS[k * TPB + tid]         = (cim1 * Dmm) * r;   // cp_in
        ckS[CKOFF + k * TPB + tid] = S * r;              // dp_in
        const int base = HF + (k << 4);
        #pragma unroll
        for (int j = 0; j < 16; ++j) FSTEP(base + j);
    }
#undef FSTEP

    // ======= phase 2: per tile (desc): recompute cp/dp, back-substitute ======
    float u = 0.0f;                                      // halo cut at top
    for (int k = NTILES - 1; k >= 0; --k) {
        const int base = HF + (k << 4);
        const float cp_in = ckS[k * TPB + tid];
        const float dp_in = ckS[CKOFF + k * TPB + tid];

        float al2 = sA[base];
        float sq2 = al2 * al2;
        float alm = sA[base - 1];
        float sm1 = alm * alm;                           // a_base
        float cpl[16], dpl[16];
        float dmm, dm, sl, qim1, qi, a2;
        {   // j = 0: fold incoming (cp_in, dp_in); local D~_{-1} = 1
            float alp1 = sA[base + 1];
            float fv   = fS[base];
            float sq1  = alp1 * alp1;
            float bi   = fmaf(al2, sq2, 1.0f);
            float D0   = fmaf(-sm1, cp_in, bi);
            float S0   = fmaf(-sm1, dp_in, fv);
            float r    = frcp(D0);
            float cj   = fmaf(2.0f, alp1, sq1);
            cpl[0] = cj * r;
            dpl[0] = S0 * r;
            dmm = 1.0f; dm = D0; sl = S0;
            qim1 = sq2; qi = sq1; a2 = alp1;
        }
        #pragma unroll
        for (int j = 1; j < 16; ++j) {
            float alp1 = sA[base + j + 1];
            float fv   = fS[base + j];
            float sq1  = alp1 * alp1;
            float bi   = fmaf(a2, qi, 1.0f);
            float cim1 = fmaf(2.0f, a2, qi);
            float t    = (qim1 * cim1) * dmm;
            float dn   = fmaf(bi, dm, -t);
            float sn   = fmaf(-qim1, sl, fv * dm);
            float r    = frcp(dn);
            float cj   = fmaf(2.0f, alp1, sq1);
            cpl[j] = (cj * dm) * r;
            dpl[j] = sn * r;
            dmm = dm; dm = dn; sl = sn;
            qim1 = qi; qi = sq1; a2 = alp1;
        }
        #pragma unroll
        for (int j = 15; j >= 0; --j) {
            u = fmaf(-cpl[j], u, dpl[j]);
            dpl[j] = u;
        }
        if (k < 8) {                                     // owned tiles only
            float4* o4 = reinterpret_cast<float4*>(
                out + (size_t)(row0 + tid) * N_COLSK + s + (k << 4));
            o4[0] = make_float4(dpl[0],  dpl[1],  dpl[2],  dpl[3]);
            o4[1] = make_float4(dpl[4],  dpl[5],  dpl[6],  dpl[7]);
            o4[2] = make_float4(dpl[8],  dpl[9],  dpl[10], dpl[11]);
            o4[3] = make_float4(dpl[12], dpl[13], dpl[14], dpl[15]);
        }
    }
}

extern "C" void kernel_launch(void* const* d_in, const int* in_sizes, int n_in,
                              void* d_out, int out_size)
{
    const float* alpha = (const float*)d_in[0];
    const float* f     = (const float*)d_in[1];
    float* out         = (float*)d_out;

    static int smem_set = 0;
    if (!smem_set) {
        cudaFuncSetAttribute(thomas_chunk_kernel,
                             cudaFuncAttributeMaxDynamicSharedMemorySize,
                             SMEM_BYTES);
        smem_set = 1;
    }

    dim3 grid(N_COLSK / L_OWN, 2048 / TPB);              // (64, 16)
    thomas_chunk_kernel<<<grid, TPB, SMEM_BYTES>>>(alpha, f, out);
}